// round 8
// baseline (speedup 1.0000x reference)
#include <cuda_runtime.h>
#include <cuda_bf16.h>
#include <math.h>
#include <stdint.h>

#define T_STEPS 64
#define BATCH   512
#define DET     1024
#define STO     128
#define EMB     1024
#define ACTD    16
#define MLP     1024
#define OUTW    1536            // 4*STO + DET
#define XIN     (STO + ACTD)    // 144
#define MIN_STD 0.1f

// ---------------- GEMM tiling ----------------
#define BM 64
#define BN 64
#define BKP 64                  // K' elements per tile (bf16)
#define ATILE_B 8192            // 64 rows * 128B
#define STAGE_B 16384           // A tile + W tile
#define NSTAGE 3
#define SMEM_TOT (NSTAGE * STAGE_B)   // 49152

typedef __nv_bfloat16 bf16;

// ---------------- scratch (device globals; no allocation allowed) ----------------
__device__ float g_gi   [BATCH*3*DET];
__device__ float g_gh   [BATCH*3*DET];
__device__ float g_q2p  [8][BATCH*2*STO];

__device__ bf16 g_hprev_h[BATCH*DET],  g_hprev_l[BATCH*DET];
__device__ bf16 g_x_h    [BATCH*DET],  g_x_l    [BATCH*DET];
__device__ bf16 g_q1_h   [BATCH*MLP],  g_q1_l   [BATCH*MLP];
__device__ bf16 g_hT_h   [(size_t)T_STEPS*BATCH*DET], g_hT_l[(size_t)T_STEPS*BATCH*DET];
__device__ bf16 g_obs_h  [(size_t)T_STEPS*BATCH*EMB], g_obs_l[(size_t)T_STEPS*BATCH*EMB];
__device__ bf16 g_p1_h   [(size_t)T_STEPS*BATCH*MLP], g_p1_l[(size_t)T_STEPS*BATCH*MLP];

// triple-K weights: [N, 3K] = [Wh | Wh | Wl]
__device__ bf16 g_Wih3[(size_t)3*DET*3*DET];
__device__ bf16 g_Whh3[(size_t)3*DET*3*DET];
__device__ bf16 g_Wq13[(size_t)MLP*3*(DET+EMB)];
__device__ bf16 g_Wq23[(size_t)2*STO*3*MLP];
__device__ bf16 g_Wp13[(size_t)MLP*3*DET];
__device__ bf16 g_Wp23[(size_t)2*STO*3*MLP];

// ---------------- math helpers ----------------
__device__ __forceinline__ float elu_f(float v)      { return v > 0.0f ? v : expm1f(v); }
__device__ __forceinline__ float softplus_f(float v) { return fmaxf(v, 0.0f) + log1pf(expf(-fabsf(v))); }
__device__ __forceinline__ float sigmoid_f(float v)  { return __fdividef(1.0f, 1.0f + __expf(-v)); }
__device__ __forceinline__ float tanh_f(float x) {
    float e = __expf(-2.0f * fabsf(x));
    float r = __fdividef(1.0f - e, 1.0f + e);
    return x < 0.0f ? -r : r;
}

__device__ __forceinline__ uint32_t smem_u32(const void* p) {
    uint32_t a;
    asm("{ .reg .u64 t; cvta.to.shared.u64 t, %1; cvt.u32.u64 %0, t; }" : "=r"(a) : "l"(p));
    return a;
}
__device__ __forceinline__ void cp16(uint32_t dst, const void* src) {
    asm volatile("cp.async.cg.shared.global [%0], [%1], 16;" :: "r"(dst), "l"(src));
}
__device__ __forceinline__ void ldsm4(uint32_t* r, uint32_t addr) {
    asm volatile("ldmatrix.sync.aligned.m8n8.x4.shared.b16 {%0,%1,%2,%3}, [%4];"
                 : "=r"(r[0]), "=r"(r[1]), "=r"(r[2]), "=r"(r[3]) : "r"(addr));
}
__device__ __forceinline__ void mma16816(float* c, const uint32_t* a, uint32_t b0, uint32_t b1) {
    asm volatile("mma.sync.aligned.m16n8k16.row.col.f32.bf16.bf16.f32 "
                 "{%0,%1,%2,%3}, {%4,%5,%6,%7}, {%8,%9}, {%0,%1,%2,%3};"
                 : "+f"(c[0]), "+f"(c[1]), "+f"(c[2]), "+f"(c[3])
                 : "r"(a[0]), "r"(a[1]), "r"(a[2]), "r"(a[3]), "r"(b0), "r"(b1));
}
// Dekker split: hi = bf16 truncation, lo = bf16(v - hi) (residual exact in bf16)
__device__ __forceinline__ void split1(float v, uint16_t& h, uint16_t& l) {
    uint32_t u = __float_as_uint(v);
    float rem  = v - __uint_as_float(u & 0xFFFF0000u);
    h = (uint16_t)(u >> 16);
    l = (uint16_t)(__float_as_uint(rem) >> 16);
}
__device__ __forceinline__ void pack2(float a, float b, uint32_t& hi, uint32_t& lo) {
    uint32_t ua = __float_as_uint(a), ub = __float_as_uint(b);
    float ra = a - __uint_as_float(ua & 0xFFFF0000u);
    float rb = b - __uint_as_float(ub & 0xFFFF0000u);
    hi = (ua >> 16) | (ub & 0xFFFF0000u);
    lo = (__float_as_uint(ra) >> 16) | (__float_as_uint(rb) & 0xFFFF0000u);
}
__device__ __forceinline__ int swoff(int row, int u) {
    return row * 128 + (((u ^ (row & 7)) & 7) << 4);
}

// ---------------- GEMM params ----------------
struct GP {
    const bf16 *Ah0, *Al0, *Ah1, *Al1;   // A = K-concat(seg0, seg1); hi/lo sources
    int lda0, lda1, k0len, K;            // K = base (pre-triple) depth
    const bf16* W3;                      // [N, 3K]
    const float* bias;
    float* C; int ldc;                   // fp32 out (epi 0/2/3)
    bf16 *Ch, *Cl; int ldch;             // bf16 hi/lo out (epi 1)
    int nkb;                             // K'-tiles per split
    int nbx;                             // valid grid.x
    int epi;                             // 0 bias | 1 bias+elu->bf16 | 2 meanstd | 3 raw partial
    int nsplit;                          // split-K count (blockIdx.z = split)
    int psz;                             // partial stride (floats) for epi 3
};

// ---------------- bf16 HMMA GEMM: C = epi(A3 @ W3^T [+ bias]) ----------------
__global__ __launch_bounds__(128, 4)
void gemm_tc(GP p0, GP p1)
{
    GP p; int split = 0;
    if (p0.nsplit > 1) { p = p0; split = blockIdx.z; }
    else               { p = blockIdx.z ? p1 : p0; }
    if ((int)blockIdx.x >= p.nbx) return;

    extern __shared__ char smem[];
    const uint32_t sbase = smem_u32(smem);
    const int tid  = threadIdx.x, wid = tid >> 5, lane = tid & 31;
    const int m0   = blockIdx.y * BM, n0 = blockIdx.x * BN;
    const int wm   = (wid & 1) * 32, wn = (wid >> 1) * 32;
    const int lrow = tid >> 1;             // 0..63
    const int ub   = (tid & 1) * 4;        // unit base 0 or 4

    float acc[2][4][4];
    #pragma unroll
    for (int i = 0; i < 2; i++)
        #pragma unroll
        for (int j = 0; j < 4; j++)
            #pragma unroll
            for (int q = 0; q < 4; q++) acc[i][j][q] = 0.0f;

    auto load_stage = [&](int st, int kb) {
        const int kp = (split * p.nkb + kb) * BKP;
        const int phase = kp / p.K;
        const int khat  = kp - phase * p.K;
        const bf16* asrc; int acol, ald;
        if (khat < p.k0len) {
            asrc = (phase == 1) ? p.Al0 : p.Ah0; acol = khat; ald = p.lda0;
        } else {
            asrc = (phase == 1) ? p.Al1 : p.Ah1; acol = khat - p.k0len; ald = p.lda1;
        }
        const bf16* ap = asrc + (size_t)(m0 + lrow) * ald + acol + ub * 8;
        const bf16* wp = p.W3 + (size_t)(n0 + lrow) * (3 * p.K) + kp + ub * 8;
        const uint32_t As = sbase + st * STAGE_B;
        const uint32_t Ws = As + ATILE_B;
        #pragma unroll
        for (int i = 0; i < 4; i++) {
            const int off = swoff(lrow, ub + i);
            cp16(As + off, ap + i * 8);
            cp16(Ws + off, wp + i * 8);
        }
        asm volatile("cp.async.commit_group;" ::: "memory");
    };

    auto compute = [&](int st) {
        const uint32_t a_s = sbase + st * STAGE_B;
        const uint32_t w_s = a_s + ATILE_B;
        #pragma unroll
        for (int k16 = 0; k16 < 4; k16++) {
            uint32_t a[2][4], b[2][4];
            const int u = k16 * 2 + (lane >> 4);
            #pragma unroll
            for (int mi = 0; mi < 2; mi++)
                ldsm4(a[mi], a_s + swoff(wm + mi * 16 + (lane & 15), u));
            #pragma unroll
            for (int nj = 0; nj < 2; nj++)
                ldsm4(b[nj], w_s + swoff(wn + nj * 16 + (lane & 15), u));
            #pragma unroll
            for (int mi = 0; mi < 2; mi++)
                #pragma unroll
                for (int ni = 0; ni < 4; ni++) {
                    const int nj = ni >> 1, s = ni & 1;
                    mma16816(acc[mi][ni], a[mi], b[nj][s], b[nj][s + 2]);
                }
        }
    };

    int fetch = 0;
    #pragma unroll
    for (int s = 0; s < NSTAGE - 1; s++)
        if (fetch < p.nkb) { load_stage(s, fetch); fetch++; }

    for (int kb = 0; kb < p.nkb; kb++) {
        if (kb < p.nkb - 1) asm volatile("cp.async.wait_group %0;" :: "n"(NSTAGE - 2) : "memory");
        else                asm volatile("cp.async.wait_group 0;" ::: "memory");
        __syncthreads();
        if (fetch < p.nkb) { load_stage(fetch % NSTAGE, fetch); fetch++; }
        compute(kb % NSTAGE);
    }

    // ---- epilogue ----
    float* Cp = p.C;
    if (p.epi == 3) Cp += (size_t)split * p.psz;
    #pragma unroll
    for (int mi = 0; mi < 2; mi++) {
        const int r0 = m0 + wm + mi * 16 + (lane >> 2);
        const int r1 = r0 + 8;
        #pragma unroll
        for (int ni = 0; ni < 4; ni++) {
            const int col = n0 + wn + ni * 8 + (lane & 3) * 2;
            float e0 = acc[mi][ni][0], e1 = acc[mi][ni][1];
            float e2 = acc[mi][ni][2], e3 = acc[mi][ni][3];
            if (p.epi != 3) {
                float b0 = p.bias[col], b1 = p.bias[col + 1];
                e0 += b0; e1 += b1; e2 += b0; e3 += b1;
            }
            if (p.epi == 1) {
                e0 = elu_f(e0); e1 = elu_f(e1); e2 = elu_f(e2); e3 = elu_f(e3);
                uint32_t h01, l01, h23, l23;
                pack2(e0, e1, h01, l01);
                pack2(e2, e3, h23, l23);
                *(uint32_t*)(p.Ch + (size_t)r0 * p.ldch + col) = h01;
                *(uint32_t*)(p.Cl + (size_t)r0 * p.ldch + col) = l01;
                *(uint32_t*)(p.Ch + (size_t)r1 * p.ldch + col) = h23;
                *(uint32_t*)(p.Cl + (size_t)r1 * p.ldch + col) = l23;
            } else {
                if (p.epi == 2 && col >= 128) {
                    e0 = softplus_f(e0) + MIN_STD; e1 = softplus_f(e1) + MIN_STD;
                    e2 = softplus_f(e2) + MIN_STD; e3 = softplus_f(e3) + MIN_STD;
                }
                *(float2*)(Cp + (size_t)r0 * p.ldc + col) = make_float2(e0, e1);
                *(float2*)(Cp + (size_t)r1 * p.ldc + col) = make_float2(e2, e3);
            }
        }
    }
}

// ---------------- weight prep: W3 = [Wh | Wh | Wl] along K ----------------
__global__ void build_w3(const float* __restrict__ src, bf16* __restrict__ dst,
                         int K, int total)
{
    int i = blockIdx.x * blockDim.x + threadIdx.x;
    if (i >= total) return;
    int n = i / K, k = i - n * K;
    uint16_t h, l;
    split1(src[i], h, l);
    bf16* row = dst + (size_t)n * 3 * K;
    row[k]         = __ushort_as_bfloat16(h);
    row[K + k]     = __ushort_as_bfloat16(h);
    row[2 * K + k] = __ushort_as_bfloat16(l);
}
__global__ void split_obs(const float* __restrict__ src, int total)
{
    int i = blockIdx.x * blockDim.x + threadIdx.x;
    if (i >= total) return;
    uint16_t h, l;
    split1(src[i], h, l);
    g_obs_h[i] = __ushort_as_bfloat16(h);
    g_obs_l[i] = __ushort_as_bfloat16(l);
}

// ---------------- elementwise kernels ----------------
// hprev0 = init_deter * nt0 (split)
__global__ void init_pre(const float* __restrict__ init_deter,
                         const float* __restrict__ nont)
{
    int idx = blockIdx.x * blockDim.x + threadIdx.x;   // BATCH*DET
    int b = idx >> 10;
    uint16_t h, l;
    split1(init_deter[idx] * nont[b], h, l);
    g_hprev_h[idx] = __ushort_as_bfloat16(h);
    g_hprev_l[idx] = __ushort_as_bfloat16(l);
}

// gates -> h; writes out[t], hT split, and hprev split for t+1
__global__ void gru_gates(const float* __restrict__ hsrc, int hstride,
                          const float* __restrict__ nont,
                          float* __restrict__ out, int t)
{
    int idx = blockIdx.x * blockDim.x + threadIdx.x;   // BATCH*DET
    int b = idx >> 10, j = idx & 1023;
    float nt = nont[t * BATCH + b];
    float hp = hsrc[(size_t)b * hstride + j] * nt;
    const float* gi = g_gi + (size_t)b * 3 * DET;
    const float* gh = g_gh + (size_t)b * 3 * DET;
    float r = sigmoid_f(gi[j]           + gh[j]);
    float z = sigmoid_f(gi[DET + j]     + gh[DET + j]);
    float n = tanh_f   (gi[2 * DET + j] + r * gh[2 * DET + j]);
    float h = (1.0f - z) * n + z * hp;
    out[((size_t)t * BATCH + b) * OUTW + 4 * STO + j] = h;
    uint16_t hh, hl;
    split1(h, hh, hl);
    size_t o = ((size_t)t * BATCH + b) * DET + j;
    g_hT_h[o] = __ushort_as_bfloat16(hh);
    g_hT_l[o] = __ushort_as_bfloat16(hl);
    if (t + 1 < T_STEPS) {
        split1(h * nont[(t + 1) * BATCH + b], hh, hl);
        g_hprev_h[idx] = __ushort_as_bfloat16(hh);
        g_hprev_l[idx] = __ushort_as_bfloat16(hl);
    }
}

// Fused: q2 split-K reduce + meanstd out + stoc sample + fp32 input layer
// x_{t+1} = elu([stoc_{t+1}*nt, a_{t+1}] @ W_in^T + b_in)  (exact fp32)
// t == -1: init mode (stoc from init_stoc, produces x_0; no q2 reduce)
// grid 64 blocks x 256 threads; each block handles 8 batch rows.
__global__ void q2x(const float* __restrict__ bq2,
                    const float* __restrict__ noise,
                    const float* __restrict__ nont,
                    const float* __restrict__ actions,
                    const float* __restrict__ init_stoc,
                    const float* __restrict__ W_in,
                    const float* __restrict__ b_in,
                    float* __restrict__ out, int t)
{
    __shared__ float xr[8][XIN];
    const int tid = threadIdx.x;
    const int b0  = blockIdx.x * 8;

    if (t >= 0) {
        __shared__ float sq[8][256];
        #pragma unroll
        for (int bb = 0; bb < 8; bb++) {
            const int b = b0 + bb;
            float s = bq2[tid];
            #pragma unroll
            for (int k = 0; k < 8; k++) s += g_q2p[k][b * 256 + tid];
            if (tid >= 128) s = softplus_f(s) + MIN_STD;
            out[((size_t)t * BATCH + b) * OUTW + 2 * STO + tid] = s;
            sq[bb][tid] = s;
        }
        __syncthreads();
        if (t + 1 >= T_STEPS) return;
        #pragma unroll
        for (int bb = 0; bb < 8; bb++) {
            const int b = b0 + bb;
            float nt = nont[(t + 1) * BATCH + b];
            if (tid < STO)
                xr[bb][tid] = (sq[bb][tid] + sq[bb][128 + tid] *
                               noise[((size_t)t * BATCH + b) * STO + tid]) * nt;
            else if (tid < XIN)
                xr[bb][tid] = actions[((size_t)(t + 1) * BATCH + b) * ACTD + (tid - STO)];
        }
    } else {
        #pragma unroll
        for (int bb = 0; bb < 8; bb++) {
            const int b = b0 + bb;
            if (tid < STO)
                xr[bb][tid] = init_stoc[b * STO + tid] * nont[b];
            else if (tid < XIN)
                xr[bb][tid] = actions[(size_t)b * ACTD + (tid - STO)];
        }
    }
    __syncthreads();

    // input layer: 1024 outputs per batch, fp32
    #pragma unroll
    for (int c = 0; c < 4; c++) {
        const int n = c * 256 + tid;
        float acc[8];
        #pragma unroll
        for (int bb = 0; bb < 8; bb++) acc[bb] = b_in[n];
        const float* w = W_in + (size_t)n * XIN;
        for (int k = 0; k < XIN; k++) {
            float wv = w[k];
            #pragma unroll
            for (int bb = 0; bb < 8; bb++) acc[bb] += wv * xr[bb][k];
        }
        #pragma unroll
        for (int bb = 0; bb < 8; bb++) {
            float e = elu_f(acc[bb]);
            uint16_t h, l;
            split1(e, h, l);
            g_x_h[(size_t)(b0 + bb) * DET + n] = __ushort_as_bfloat16(h);
            g_x_l[(size_t)(b0 + bb) * DET + n] = __ushort_as_bfloat16(l);
        }
    }
}

// ---------------- launch ----------------
extern "C" void kernel_launch(void* const* d_in, const int* in_sizes, int n_in,
                              void* d_out, int out_size)
{
    const float* actions    = (const float*)d_in[0];
    const float* nont       = (const float*)d_in[1];
    const float* obs        = (const float*)d_in[2];
    const float* noise      = (const float*)d_in[3];
    const float* init_stoc  = (const float*)d_in[4];
    const float* init_deter = (const float*)d_in[5];
    const float* W_in = (const float*)d_in[6];
    const float* b_in = (const float*)d_in[7];
    const float* W_ih = (const float*)d_in[8];
    const float* W_hh = (const float*)d_in[9];
    const float* b_ih = (const float*)d_in[10];
    const float* b_hh = (const float*)d_in[11];
    const float* Wp1  = (const float*)d_in[12];
    const float* bp1  = (const float*)d_in[13];
    const float* Wp2  = (const float*)d_in[14];
    const float* bp2  = (const float*)d_in[15];
    const float* Wq1  = (const float*)d_in[16];
    const float* bq1  = (const float*)d_in[17];
    const float* Wq2  = (const float*)d_in[18];
    const float* bq2  = (const float*)d_in[19];
    float* out = (float*)d_out;

    float *p_gi, *p_gh, *p_q2p;
    cudaGetSymbolAddress((void**)&p_gi,  g_gi);
    cudaGetSymbolAddress((void**)&p_gh,  g_gh);
    cudaGetSymbolAddress((void**)&p_q2p, g_q2p);

    bf16 *hprev_h, *hprev_l, *x_h, *x_l, *q1_h, *q1_l;
    bf16 *hT_h, *hT_l, *obs_h, *obs_l, *p1_h, *p1_l;
    bf16 *wih3, *whh3, *wq13, *wq23, *wp13, *wp23;
    cudaGetSymbolAddress((void**)&hprev_h, g_hprev_h);
    cudaGetSymbolAddress((void**)&hprev_l, g_hprev_l);
    cudaGetSymbolAddress((void**)&x_h,     g_x_h);
    cudaGetSymbolAddress((void**)&x_l,     g_x_l);
    cudaGetSymbolAddress((void**)&q1_h,    g_q1_h);
    cudaGetSymbolAddress((void**)&q1_l,    g_q1_l);
    cudaGetSymbolAddress((void**)&hT_h,    g_hT_h);
    cudaGetSymbolAddress((void**)&hT_l,    g_hT_l);
    cudaGetSymbolAddress((void**)&obs_h,   g_obs_h);
    cudaGetSymbolAddress((void**)&obs_l,   g_obs_l);
    cudaGetSymbolAddress((void**)&p1_h,    g_p1_h);
    cudaGetSymbolAddress((void**)&p1_l,    g_p1_l);
    cudaGetSymbolAddress((void**)&wih3,    g_Wih3);
    cudaGetSymbolAddress((void**)&whh3,    g_Whh3);
    cudaGetSymbolAddress((void**)&wq13,    g_Wq13);
    cudaGetSymbolAddress((void**)&wq23,    g_Wq23);
    cudaGetSymbolAddress((void**)&wp13,    g_Wp13);
    cudaGetSymbolAddress((void**)&wp23,    g_Wp23);

    cudaFuncSetAttribute(gemm_tc, cudaFuncAttributeMaxDynamicSharedMemorySize, SMEM_TOT);

    const int BIG = 1 << 28;
    GP ggh = { hprev_h, hprev_l, hprev_h, hprev_l, DET, DET, BIG, DET,
               whh3, b_hh, p_gh, 3*DET, nullptr, nullptr, 0, 48, 48, 0, 1, 0 };
    GP ggi = { x_h, x_l, x_h, x_l, DET, DET, BIG, DET,
               wih3, b_ih, p_gi, 3*DET, nullptr, nullptr, 0, 48, 48, 0, 1, 0 };
    GP gq2 = { q1_h, q1_l, q1_h, q1_l, MLP, MLP, BIG, MLP,
               wq23, nullptr, p_q2p, 2*STO, nullptr, nullptr, 0, 6, 4, 3, 8, BATCH*2*STO };

    // ---- prelude (ordered so a main GEMM sits at launches #4-#6 for ncu) ----
    build_w3<<<(3*DET*DET + 255)/256, 256>>>(W_hh, whh3, DET, 3*DET*DET);          // 1
    build_w3<<<(3*DET*DET + 255)/256, 256>>>(W_ih, wih3, DET, 3*DET*DET);          // 2
    init_pre<<<BATCH * DET / 256, 256>>>(init_deter, nont);                        // 3
    q2x<<<64, 256>>>(bq2, noise, nont, actions, init_stoc, W_in, b_in, out, -1);   // 4 -> x0
    gemm_tc<<<dim3(48, 8, 2), 128, SMEM_TOT>>>(ggh, ggi);                          // 5: gh0 + gi0
    split_obs<<<(T_STEPS*BATCH*EMB + 255)/256, 256>>>(obs, T_STEPS*BATCH*EMB);     // 6
    build_w3<<<(MLP*(DET+EMB) + 255)/256, 256>>>(Wq1, wq13, DET+EMB, MLP*(DET+EMB));
    build_w3<<<(2*STO*MLP + 255)/256, 256>>>(Wq2, wq23, MLP, 2*STO*MLP);
    build_w3<<<(MLP*DET + 255)/256, 256>>>(Wp1, wp13, DET, MLP*DET);
    build_w3<<<(2*STO*MLP + 255)/256, 256>>>(Wp2, wp23, MLP, 2*STO*MLP);

    for (int t = 0; t < T_STEPS; t++) {
        // gates_t (consumes gi_t, gh_t; produces h_t, hT_t, hprev_{t+1})
        const float* hsrc = (t == 0) ? init_deter
                                     : out + (size_t)(t - 1) * BATCH * OUTW + 4 * STO;
        gru_gates<<<BATCH * DET / 256, 256>>>(hsrc, (t == 0) ? DET : OUTW, nont, out, t);

        // dual(q1_t, gh_{t+1}) — both depend only on gates_t
        GP gq1 = { hT_h + (size_t)t*BATCH*DET, hT_l + (size_t)t*BATCH*DET,
                   obs_h + (size_t)t*BATCH*EMB, obs_l + (size_t)t*BATCH*EMB,
                   DET, EMB, DET, DET+EMB,
                   wq13, bq1, nullptr, 0, q1_h, q1_l, MLP, 96, 16, 1, 1, 0 };
        if (t + 1 < T_STEPS)
            gemm_tc<<<dim3(48, 8, 2), 128, SMEM_TOT>>>(gq1, ggh);
        else
            gemm_tc<<<dim3(16, 8, 1), 128, SMEM_TOT>>>(gq1, gq1);

        // q2 split-K8 partials
        gemm_tc<<<dim3(4, 8, 8), 128, SMEM_TOT>>>(gq2, gq2);

        // fused: q2 reduce + qm/qs out + stoc + fp32 input layer -> x_{t+1}
        q2x<<<64, 256>>>(bq2, noise, nont, actions, init_stoc, W_in, b_in, out, t);

        // gi_{t+1}
        if (t + 1 < T_STEPS)
            gemm_tc<<<dim3(48, 8, 1), 128, SMEM_TOT>>>(ggi, ggi);
    }

    // ---- prior head, batched over all T (off the recurrence) ----
    GP gp1 = { hT_h, hT_l, hT_h, hT_l, DET, DET, BIG, DET,
               wp13, bp1, nullptr, 0, p1_h, p1_l, MLP, 48, 16, 1, 1, 0 };
    gemm_tc<<<dim3(16, 512, 1), 128, SMEM_TOT>>>(gp1, gp1);

    GP gp2 = { p1_h, p1_l, p1_h, p1_l, MLP, MLP, BIG, MLP,
               wp23, bp2, out, OUTW, nullptr, nullptr, 0, 48, 4, 2, 1, 0 };
    gemm_tc<<<dim3(4, 512, 1), 128, SMEM_TOT>>>(gp2, gp2);
}

// round 9
// speedup vs baseline: 1.0880x; 1.0880x over previous
#include <cuda_runtime.h>
#include <cuda_bf16.h>
#include <math.h>
#include <stdint.h>

#define T_STEPS 64
#define BATCH   512
#define DET     1024
#define STO     128
#define EMB     1024
#define ACTD    16
#define MLP     1024
#define OUTW    1536            // 4*STO + DET
#define XIN     (STO + ACTD)    // 144
#define MIN_STD 0.1f

// ---------------- GEMM tiling ----------------
#define BM 64
#define BN 64
#define BKP 64                  // K' elements per tile (bf16)
#define ATILE_B 8192            // 64 rows * 128B
#define STAGE_B 16384           // A tile + W tile
#define NSTAGE 3
#define SMEM_TOT (NSTAGE * STAGE_B)   // 49152

typedef __nv_bfloat16 bf16;

// ---------------- scratch (device globals; no allocation allowed) ----------------
__device__ float g_gi   [BATCH*3*DET];
__device__ float g_gh   [BATCH*3*DET];
__device__ float g_q2p  [8][BATCH*2*STO];
__device__ float g_q1p  [2][BATCH*MLP];

__device__ bf16 g_hprev_h[BATCH*DET],  g_hprev_l[BATCH*DET];
__device__ bf16 g_x_h    [BATCH*DET],  g_x_l    [BATCH*DET];
__device__ bf16 g_q1_h   [BATCH*MLP],  g_q1_l   [BATCH*MLP];
__device__ bf16 g_hT_h   [(size_t)T_STEPS*BATCH*DET], g_hT_l[(size_t)T_STEPS*BATCH*DET];
__device__ bf16 g_obs_h  [(size_t)T_STEPS*BATCH*EMB], g_obs_l[(size_t)T_STEPS*BATCH*EMB];
__device__ bf16 g_p1_h   [(size_t)T_STEPS*BATCH*MLP], g_p1_l[(size_t)T_STEPS*BATCH*MLP];

// triple-K weights: [N, 3K] = [Wh | Wh | Wl]
__device__ bf16 g_Wih3[(size_t)3*DET*3*DET];
__device__ bf16 g_Whh3[(size_t)3*DET*3*DET];
__device__ bf16 g_Wq13[(size_t)MLP*3*(DET+EMB)];
__device__ bf16 g_Wq23[(size_t)2*STO*3*MLP];
__device__ bf16 g_Wp13[(size_t)MLP*3*DET];
__device__ bf16 g_Wp23[(size_t)2*STO*3*MLP];

// ---------------- math helpers ----------------
__device__ __forceinline__ float elu_f(float v)      { return v > 0.0f ? v : expm1f(v); }
__device__ __forceinline__ float softplus_f(float v) { return fmaxf(v, 0.0f) + log1pf(expf(-fabsf(v))); }
__device__ __forceinline__ float sigmoid_f(float v)  { return __fdividef(1.0f, 1.0f + __expf(-v)); }
__device__ __forceinline__ float tanh_f(float x) {
    float e = __expf(-2.0f * fabsf(x));
    float r = __fdividef(1.0f - e, 1.0f + e);
    return x < 0.0f ? -r : r;
}

__device__ __forceinline__ uint32_t smem_u32(const void* p) {
    uint32_t a;
    asm("{ .reg .u64 t; cvta.to.shared.u64 t, %1; cvt.u32.u64 %0, t; }" : "=r"(a) : "l"(p));
    return a;
}
__device__ __forceinline__ void cp16(uint32_t dst, const void* src) {
    asm volatile("cp.async.cg.shared.global [%0], [%1], 16;" :: "r"(dst), "l"(src));
}
__device__ __forceinline__ void ldsm4(uint32_t* r, uint32_t addr) {
    asm volatile("ldmatrix.sync.aligned.m8n8.x4.shared.b16 {%0,%1,%2,%3}, [%4];"
                 : "=r"(r[0]), "=r"(r[1]), "=r"(r[2]), "=r"(r[3]) : "r"(addr));
}
__device__ __forceinline__ void mma16816(float* c, const uint32_t* a, uint32_t b0, uint32_t b1) {
    asm volatile("mma.sync.aligned.m16n8k16.row.col.f32.bf16.bf16.f32 "
                 "{%0,%1,%2,%3}, {%4,%5,%6,%7}, {%8,%9}, {%0,%1,%2,%3};"
                 : "+f"(c[0]), "+f"(c[1]), "+f"(c[2]), "+f"(c[3])
                 : "r"(a[0]), "r"(a[1]), "r"(a[2]), "r"(a[3]), "r"(b0), "r"(b1));
}
// Dekker split: hi = bf16 truncation, lo = bf16(v - hi) (residual exact in bf16)
__device__ __forceinline__ void split1(float v, uint16_t& h, uint16_t& l) {
    uint32_t u = __float_as_uint(v);
    float rem  = v - __uint_as_float(u & 0xFFFF0000u);
    h = (uint16_t)(u >> 16);
    l = (uint16_t)(__float_as_uint(rem) >> 16);
}
__device__ __forceinline__ void pack2(float a, float b, uint32_t& hi, uint32_t& lo) {
    uint32_t ua = __float_as_uint(a), ub = __float_as_uint(b);
    float ra = a - __uint_as_float(ua & 0xFFFF0000u);
    float rb = b - __uint_as_float(ub & 0xFFFF0000u);
    hi = (ua >> 16) | (ub & 0xFFFF0000u);
    lo = (__float_as_uint(ra) >> 16) | (__float_as_uint(rb) & 0xFFFF0000u);
}
__device__ __forceinline__ int swoff(int row, int u) {
    return row * 128 + (((u ^ (row & 7)) & 7) << 4);
}

// ---------------- GEMM params ----------------
struct GP {
    const bf16 *Ah0, *Al0, *Ah1, *Al1;   // A = K-concat(seg0, seg1); hi/lo sources
    int lda0, lda1, k0len, K;            // K = base (pre-triple) depth
    const bf16* W3;                      // [N, 3K]
    const float* bias;
    float* C; int ldc;                   // fp32 out (epi 0/2/3)
    bf16 *Ch, *Cl; int ldch;             // bf16 hi/lo out (epi 1)
    int nkb;                             // K'-tiles per split
    int nbx;                             // valid grid.x
    int epi;                             // 0 bias | 1 bias+elu->bf16 | 2 meanstd | 3 raw partial
    int nsplit;                          // split-K count (z slices owned by this GP)
    int psz;                             // partial stride (floats) for epi 3
};

// ---------------- bf16 HMMA GEMM: C = epi(A3 @ W3^T [+ bias]) ----------------
// z-dispatch: z < p0.nsplit -> p0 (split = z); else -> p1 (split 0)
__global__ __launch_bounds__(128, 4)
void gemm_tc(GP p0, GP p1)
{
    GP p; int split;
    if ((int)blockIdx.z < p0.nsplit) { p = p0; split = blockIdx.z; }
    else                             { p = p1; split = 0; }
    if ((int)blockIdx.x >= p.nbx) return;

    extern __shared__ char smem[];
    const uint32_t sbase = smem_u32(smem);
    const int tid  = threadIdx.x, wid = tid >> 5, lane = tid & 31;
    const int m0   = blockIdx.y * BM, n0 = blockIdx.x * BN;
    const int wm   = (wid & 1) * 32, wn = (wid >> 1) * 32;
    const int lrow = tid >> 1;             // 0..63
    const int ub   = (tid & 1) * 4;        // unit base 0 or 4

    float acc[2][4][4];
    #pragma unroll
    for (int i = 0; i < 2; i++)
        #pragma unroll
        for (int j = 0; j < 4; j++)
            #pragma unroll
            for (int q = 0; q < 4; q++) acc[i][j][q] = 0.0f;

    auto load_stage = [&](int st, int kb) {
        const int kp = (split * p.nkb + kb) * BKP;
        const int phase = kp / p.K;
        const int khat  = kp - phase * p.K;
        const bf16* asrc; int acol, ald;
        if (khat < p.k0len) {
            asrc = (phase == 1) ? p.Al0 : p.Ah0; acol = khat; ald = p.lda0;
        } else {
            asrc = (phase == 1) ? p.Al1 : p.Ah1; acol = khat - p.k0len; ald = p.lda1;
        }
        const bf16* ap = asrc + (size_t)(m0 + lrow) * ald + acol + ub * 8;
        const bf16* wp = p.W3 + (size_t)(n0 + lrow) * (3 * p.K) + kp + ub * 8;
        const uint32_t As = sbase + st * STAGE_B;
        const uint32_t Ws = As + ATILE_B;
        #pragma unroll
        for (int i = 0; i < 4; i++) {
            const int off = swoff(lrow, ub + i);
            cp16(As + off, ap + i * 8);
            cp16(Ws + off, wp + i * 8);
        }
        asm volatile("cp.async.commit_group;" ::: "memory");
    };

    auto compute = [&](int st) {
        const uint32_t a_s = sbase + st * STAGE_B;
        const uint32_t w_s = a_s + ATILE_B;
        #pragma unroll
        for (int k16 = 0; k16 < 4; k16++) {
            uint32_t a[2][4], b[2][4];
            const int u = k16 * 2 + (lane >> 4);
            #pragma unroll
            for (int mi = 0; mi < 2; mi++)
                ldsm4(a[mi], a_s + swoff(wm + mi * 16 + (lane & 15), u));
            #pragma unroll
            for (int nj = 0; nj < 2; nj++)
                ldsm4(b[nj], w_s + swoff(wn + nj * 16 + (lane & 15), u));
            #pragma unroll
            for (int mi = 0; mi < 2; mi++)
                #pragma unroll
                for (int ni = 0; ni < 4; ni++) {
                    const int nj = ni >> 1, s = ni & 1;
                    mma16816(acc[mi][ni], a[mi], b[nj][s], b[nj][s + 2]);
                }
        }
    };

    int fetch = 0;
    #pragma unroll
    for (int s = 0; s < NSTAGE - 1; s++)
        if (fetch < p.nkb) { load_stage(s, fetch); fetch++; }

    for (int kb = 0; kb < p.nkb; kb++) {
        if (kb < p.nkb - 1) asm volatile("cp.async.wait_group %0;" :: "n"(NSTAGE - 2) : "memory");
        else                asm volatile("cp.async.wait_group 0;" ::: "memory");
        __syncthreads();
        if (fetch < p.nkb) { load_stage(fetch % NSTAGE, fetch); fetch++; }
        compute(kb % NSTAGE);
    }

    // ---- epilogue ----
    float* Cp = p.C;
    if (p.epi == 3) Cp += (size_t)split * p.psz;
    #pragma unroll
    for (int mi = 0; mi < 2; mi++) {
        const int r0 = m0 + wm + mi * 16 + (lane >> 2);
        const int r1 = r0 + 8;
        #pragma unroll
        for (int ni = 0; ni < 4; ni++) {
            const int col = n0 + wn + ni * 8 + (lane & 3) * 2;
            float e0 = acc[mi][ni][0], e1 = acc[mi][ni][1];
            float e2 = acc[mi][ni][2], e3 = acc[mi][ni][3];
            if (p.epi != 3) {
                float b0 = p.bias[col], b1 = p.bias[col + 1];
                e0 += b0; e1 += b1; e2 += b0; e3 += b1;
            }
            if (p.epi == 1) {
                e0 = elu_f(e0); e1 = elu_f(e1); e2 = elu_f(e2); e3 = elu_f(e3);
                uint32_t h01, l01, h23, l23;
                pack2(e0, e1, h01, l01);
                pack2(e2, e3, h23, l23);
                *(uint32_t*)(p.Ch + (size_t)r0 * p.ldch + col) = h01;
                *(uint32_t*)(p.Cl + (size_t)r0 * p.ldch + col) = l01;
                *(uint32_t*)(p.Ch + (size_t)r1 * p.ldch + col) = h23;
                *(uint32_t*)(p.Cl + (size_t)r1 * p.ldch + col) = l23;
            } else {
                if (p.epi == 2 && col >= 128) {
                    e0 = softplus_f(e0) + MIN_STD; e1 = softplus_f(e1) + MIN_STD;
                    e2 = softplus_f(e2) + MIN_STD; e3 = softplus_f(e3) + MIN_STD;
                }
                *(float2*)(Cp + (size_t)r0 * p.ldc + col) = make_float2(e0, e1);
                *(float2*)(Cp + (size_t)r1 * p.ldc + col) = make_float2(e2, e3);
            }
        }
    }
}

// ---------------- weight prep: W3 = [Wh | Wh | Wl] along K ----------------
__global__ void build_w3(const float* __restrict__ src, bf16* __restrict__ dst,
                         int K, int total)
{
    int i = blockIdx.x * blockDim.x + threadIdx.x;
    if (i >= total) return;
    int n = i / K, k = i - n * K;
    uint16_t h, l;
    split1(src[i], h, l);
    bf16* row = dst + (size_t)n * 3 * K;
    row[k]         = __ushort_as_bfloat16(h);
    row[K + k]     = __ushort_as_bfloat16(h);
    row[2 * K + k] = __ushort_as_bfloat16(l);
}
__global__ void split_obs(const float* __restrict__ src, int total)
{
    int i = blockIdx.x * blockDim.x + threadIdx.x;
    if (i >= total) return;
    uint16_t h, l;
    split1(src[i], h, l);
    g_obs_h[i] = __ushort_as_bfloat16(h);
    g_obs_l[i] = __ushort_as_bfloat16(l);
}

// ---------------- elementwise kernels ----------------
// hprev0 = init_deter * nt0 (split)
__global__ void init_pre(const float* __restrict__ init_deter,
                         const float* __restrict__ nont)
{
    int idx = blockIdx.x * blockDim.x + threadIdx.x;   // BATCH*DET
    int b = idx >> 10;
    uint16_t h, l;
    split1(init_deter[idx] * nont[b], h, l);
    g_hprev_h[idx] = __ushort_as_bfloat16(h);
    g_hprev_l[idx] = __ushort_as_bfloat16(l);
}

// gates -> h; writes out[t], hT split, and hprev split for t+1
__global__ void gru_gates(const float* __restrict__ hsrc, int hstride,
                          const float* __restrict__ nont,
                          float* __restrict__ out, int t)
{
    int idx = blockIdx.x * blockDim.x + threadIdx.x;   // BATCH*DET
    int b = idx >> 10, j = idx & 1023;
    float nt = nont[t * BATCH + b];
    float hp = hsrc[(size_t)b * hstride + j] * nt;
    const float* gi = g_gi + (size_t)b * 3 * DET;
    const float* gh = g_gh + (size_t)b * 3 * DET;
    float r = sigmoid_f(gi[j]           + gh[j]);
    float z = sigmoid_f(gi[DET + j]     + gh[DET + j]);
    float n = tanh_f   (gi[2 * DET + j] + r * gh[2 * DET + j]);
    float h = (1.0f - z) * n + z * hp;
    out[((size_t)t * BATCH + b) * OUTW + 4 * STO + j] = h;
    uint16_t hh, hl;
    split1(h, hh, hl);
    size_t o = ((size_t)t * BATCH + b) * DET + j;
    g_hT_h[o] = __ushort_as_bfloat16(hh);
    g_hT_l[o] = __ushort_as_bfloat16(hl);
    if (t + 1 < T_STEPS) {
        split1(h * nont[(t + 1) * BATCH + b], hh, hl);
        g_hprev_h[idx] = __ushort_as_bfloat16(hh);
        g_hprev_l[idx] = __ushort_as_bfloat16(hl);
    }
}

// q1 = elu(p0 + p1 + bias) -> bf16 hi/lo pair
__global__ void q1red(const float* __restrict__ bias)
{
    int i = blockIdx.x * blockDim.x + threadIdx.x;     // BATCH*MLP/4
    float4 a = ((const float4*)g_q1p[0])[i];
    float4 c = ((const float4*)g_q1p[1])[i];
    int n = (i & (MLP / 4 - 1)) * 4;
    float4 bs = *(const float4*)(bias + n);
    float e0 = elu_f(a.x + c.x + bs.x);
    float e1 = elu_f(a.y + c.y + bs.y);
    float e2 = elu_f(a.z + c.z + bs.z);
    float e3 = elu_f(a.w + c.w + bs.w);
    uint32_t h01, l01, h23, l23;
    pack2(e0, e1, h01, l01);
    pack2(e2, e3, h23, l23);
    *(uint32_t*)(g_q1_h + (size_t)i * 4)     = h01;
    *(uint32_t*)(g_q1_h + (size_t)i * 4 + 2) = h23;
    *(uint32_t*)(g_q1_l + (size_t)i * 4)     = l01;
    *(uint32_t*)(g_q1_l + (size_t)i * 4 + 2) = l23;
}

// Fused: q2 split-K reduce + meanstd out + stoc sample + fp32 input layer
// x_{t+1} = elu([stoc_{t+1}*nt, a_{t+1}] @ W_in^T + b_in)  (exact fp32)
// t == -1: init mode (stoc from init_stoc, produces x_0; no q2 reduce)
// grid 128 blocks x 256 threads; 4 batch rows per block.
__global__ void q2x(const float* __restrict__ bq2,
                    const float* __restrict__ noise,
                    const float* __restrict__ nont,
                    const float* __restrict__ actions,
                    const float* __restrict__ init_stoc,
                    const float* __restrict__ W_in,
                    const float* __restrict__ b_in,
                    float* __restrict__ out, int t)
{
    __shared__ float xr[4][XIN];
    const int tid = threadIdx.x;
    const int b0  = blockIdx.x * 4;

    if (t >= 0) {
        __shared__ float sq[4][256];
        #pragma unroll
        for (int bb = 0; bb < 4; bb++) {
            const int b = b0 + bb;
            float s = bq2[tid];
            #pragma unroll
            for (int k = 0; k < 8; k++) s += g_q2p[k][b * 256 + tid];
            if (tid >= 128) s = softplus_f(s) + MIN_STD;
            out[((size_t)t * BATCH + b) * OUTW + 2 * STO + tid] = s;
            sq[bb][tid] = s;
        }
        __syncthreads();
        if (t + 1 >= T_STEPS) return;
        #pragma unroll
        for (int bb = 0; bb < 4; bb++) {
            const int b = b0 + bb;
            float nt = nont[(t + 1) * BATCH + b];
            if (tid < STO)
                xr[bb][tid] = (sq[bb][tid] + sq[bb][128 + tid] *
                               noise[((size_t)t * BATCH + b) * STO + tid]) * nt;
            else if (tid < XIN)
                xr[bb][tid] = actions[((size_t)(t + 1) * BATCH + b) * ACTD + (tid - STO)];
        }
    } else {
        #pragma unroll
        for (int bb = 0; bb < 4; bb++) {
            const int b = b0 + bb;
            if (tid < STO)
                xr[bb][tid] = init_stoc[b * STO + tid] * nont[b];
            else if (tid < XIN)
                xr[bb][tid] = actions[(size_t)b * ACTD + (tid - STO)];
        }
    }
    __syncthreads();

    // input layer: 1024 outputs x 4 batch rows, exact fp32
    #pragma unroll
    for (int c = 0; c < 4; c++) {
        const int n = c * 256 + tid;
        float acc0 = b_in[n], acc1 = acc0, acc2 = acc0, acc3 = acc0;
        const float* w = W_in + (size_t)n * XIN;
        #pragma unroll 4
        for (int k = 0; k < XIN; k++) {
            float wv = w[k];
            acc0 += wv * xr[0][k];
            acc1 += wv * xr[1][k];
            acc2 += wv * xr[2][k];
            acc3 += wv * xr[3][k];
        }
        float e[4] = { elu_f(acc0), elu_f(acc1), elu_f(acc2), elu_f(acc3) };
        #pragma unroll
        for (int bb = 0; bb < 4; bb++) {
            uint16_t h, l;
            split1(e[bb], h, l);
            g_x_h[(size_t)(b0 + bb) * DET + n] = __ushort_as_bfloat16(h);
            g_x_l[(size_t)(b0 + bb) * DET + n] = __ushort_as_bfloat16(l);
        }
    }
}

// ---------------- launch ----------------
extern "C" void kernel_launch(void* const* d_in, const int* in_sizes, int n_in,
                              void* d_out, int out_size)
{
    const float* actions    = (const float*)d_in[0];
    const float* nont       = (const float*)d_in[1];
    const float* obs        = (const float*)d_in[2];
    const float* noise      = (const float*)d_in[3];
    const float* init_stoc  = (const float*)d_in[4];
    const float* init_deter = (const float*)d_in[5];
    const float* W_in = (const float*)d_in[6];
    const float* b_in = (const float*)d_in[7];
    const float* W_ih = (const float*)d_in[8];
    const float* W_hh = (const float*)d_in[9];
    const float* b_ih = (const float*)d_in[10];
    const float* b_hh = (const float*)d_in[11];
    const float* Wp1  = (const float*)d_in[12];
    const float* bp1  = (const float*)d_in[13];
    const float* Wp2  = (const float*)d_in[14];
    const float* bp2  = (const float*)d_in[15];
    const float* Wq1  = (const float*)d_in[16];
    const float* bq1  = (const float*)d_in[17];
    const float* Wq2  = (const float*)d_in[18];
    const float* bq2  = (const float*)d_in[19];
    float* out = (float*)d_out;

    float *p_gi, *p_gh, *p_q2p, *p_q1p;
    cudaGetSymbolAddress((void**)&p_gi,  g_gi);
    cudaGetSymbolAddress((void**)&p_gh,  g_gh);
    cudaGetSymbolAddress((void**)&p_q2p, g_q2p);
    cudaGetSymbolAddress((void**)&p_q1p, g_q1p);

    bf16 *hprev_h, *hprev_l, *x_h, *x_l, *q1_h, *q1_l;
    bf16 *hT_h, *hT_l, *obs_h, *obs_l, *p1_h, *p1_l;
    bf16 *wih3, *whh3, *wq13, *wq23, *wp13, *wp23;
    cudaGetSymbolAddress((void**)&hprev_h, g_hprev_h);
    cudaGetSymbolAddress((void**)&hprev_l, g_hprev_l);
    cudaGetSymbolAddress((void**)&x_h,     g_x_h);
    cudaGetSymbolAddress((void**)&x_l,     g_x_l);
    cudaGetSymbolAddress((void**)&q1_h,    g_q1_h);
    cudaGetSymbolAddress((void**)&q1_l,    g_q1_l);
    cudaGetSymbolAddress((void**)&hT_h,    g_hT_h);
    cudaGetSymbolAddress((void**)&hT_l,    g_hT_l);
    cudaGetSymbolAddress((void**)&obs_h,   g_obs_h);
    cudaGetSymbolAddress((void**)&obs_l,   g_obs_l);
    cudaGetSymbolAddress((void**)&p1_h,    g_p1_h);
    cudaGetSymbolAddress((void**)&p1_l,    g_p1_l);
    cudaGetSymbolAddress((void**)&wih3,    g_Wih3);
    cudaGetSymbolAddress((void**)&whh3,    g_Whh3);
    cudaGetSymbolAddress((void**)&wq13,    g_Wq13);
    cudaGetSymbolAddress((void**)&wq23,    g_Wq23);
    cudaGetSymbolAddress((void**)&wp13,    g_Wp13);
    cudaGetSymbolAddress((void**)&wp23,    g_Wp23);

    cudaFuncSetAttribute(gemm_tc, cudaFuncAttributeMaxDynamicSharedMemorySize, SMEM_TOT);

    const int BIG = 1 << 28;
    GP ggh = { hprev_h, hprev_l, hprev_h, hprev_l, DET, DET, BIG, DET,
               whh3, b_hh, p_gh, 3*DET, nullptr, nullptr, 0, 48, 48, 0, 1, 0 };
    GP ggi = { x_h, x_l, x_h, x_l, DET, DET, BIG, DET,
               wih3, b_ih, p_gi, 3*DET, nullptr, nullptr, 0, 48, 48, 0, 1, 0 };
    GP gq2 = { q1_h, q1_l, q1_h, q1_l, MLP, MLP, BIG, MLP,
               wq23, nullptr, p_q2p, 2*STO, nullptr, nullptr, 0, 6, 4, 3, 8, BATCH*2*STO };

    // ---- prelude; launch #4 = solo ggh GEMM (the one ncu profiles) ----
    build_w3<<<(3*DET*DET + 255)/256, 256>>>(W_hh, whh3, DET, 3*DET*DET);          // 1
    init_pre<<<BATCH * DET / 256, 256>>>(init_deter, nont);                        // 2
    split_obs<<<(T_STEPS*BATCH*EMB + 255)/256, 256>>>(obs, T_STEPS*BATCH*EMB);     // 3
    gemm_tc<<<dim3(48, 8, 1), 128, SMEM_TOT>>>(ggh, ggh);                          // 4 -> gh0 (PROFILED)
    build_w3<<<(3*DET*DET + 255)/256, 256>>>(W_ih, wih3, DET, 3*DET*DET);          // 5
    q2x<<<128, 256>>>(bq2, noise, nont, actions, init_stoc, W_in, b_in, out, -1);  // 6 -> x0
    gemm_tc<<<dim3(48, 8, 1), 128, SMEM_TOT>>>(ggi, ggi);                          // 7 -> gi0
    build_w3<<<(MLP*(DET+EMB) + 255)/256, 256>>>(Wq1, wq13, DET+EMB, MLP*(DET+EMB));
    build_w3<<<(2*STO*MLP + 255)/256, 256>>>(Wq2, wq23, MLP, 2*STO*MLP);
    build_w3<<<(MLP*DET + 255)/256, 256>>>(Wp1, wp13, DET, MLP*DET);
    build_w3<<<(2*STO*MLP + 255)/256, 256>>>(Wp2, wp23, MLP, 2*STO*MLP);

    for (int t = 0; t < T_STEPS; t++) {
        // gates_t (consumes gi_t, gh_t; produces h_t, hT_t, hprev_{t+1})
        const float* hsrc = (t == 0) ? init_deter
                                     : out + (size_t)(t - 1) * BATCH * OUTW + 4 * STO;
        gru_gates<<<BATCH * DET / 256, 256>>>(hsrc, (t == 0) ? DET : OUTW, nont, out, t);

        // uniform-wave pack: q1 split-K2 (fp32 partials) + gh_{t+1}; all CTAs 48 tiles
        GP gq1s = { hT_h + (size_t)t*BATCH*DET, hT_l + (size_t)t*BATCH*DET,
                    obs_h + (size_t)t*BATCH*EMB, obs_l + (size_t)t*BATCH*EMB,
                    DET, EMB, DET, DET+EMB,
                    wq13, nullptr, p_q1p, MLP, nullptr, nullptr, 0, 48, 16, 3, 2, BATCH*MLP };
        if (t + 1 < T_STEPS)
            gemm_tc<<<dim3(48, 8, 3), 128, SMEM_TOT>>>(gq1s, ggh);
        else
            gemm_tc<<<dim3(16, 8, 2), 128, SMEM_TOT>>>(gq1s, gq1s);

        // q1 = elu(p0+p1+bq1) -> bf16 pair
        q1red<<<BATCH * MLP / 4 / 256, 256>>>(bq1);

        // q2 split-K8 partials
        gemm_tc<<<dim3(4, 8, 8), 128, SMEM_TOT>>>(gq2, gq2);

        // fused: q2 reduce + qm/qs out + stoc + fp32 input layer -> x_{t+1}
        q2x<<<128, 256>>>(bq2, noise, nont, actions, init_stoc, W_in, b_in, out, t);

        // gi_{t+1}
        if (t + 1 < T_STEPS)
            gemm_tc<<<dim3(48, 8, 1), 128, SMEM_TOT>>>(ggi, ggi);
    }

    // ---- prior head, batched over all T (off the recurrence) ----
    GP gp1 = { hT_h, hT_l, hT_h, hT_l, DET, DET, BIG, DET,
               wp13, bp1, nullptr, 0, p1_h, p1_l, MLP, 48, 16, 1, 1, 0 };
    gemm_tc<<<dim3(16, 512, 1), 128, SMEM_TOT>>>(gp1, gp1);

    GP gp2 = { p1_h, p1_l, p1_h, p1_l, MLP, MLP, BIG, MLP,
               wp23, bp2, out, OUTW, nullptr, nullptr, 0, 48, 4, 2, 1, 0 };
    gemm_tc<<<dim3(4, 512, 1), 128, SMEM_TOT>>>(gp2, gp2);
}